// round 17
// baseline (speedup 1.0000x reference)
#include <cuda_runtime.h>
#include <cstdint>
#include <cstddef>

// ---------------- tile config ----------------
#define M_TILE 64
#define N_OUT  256
#define K_DIM  512
#define KC     16                  // K per chunk = one fp16 MMA k-step
#define NCHUNK (K_DIM / KC)        // 32
#define ASTH   24                  // f16 row stride (16 data + 8 pad) -> conflict-free LDS.32
#define NTHREADS 256

// ctrl region (floats)
#define OFF_BIAS 0                 // 256
#define OFF_PT   256               // [4][64]
#define OFF_PZZ  512               // [4][64]
#define OFF_AB   768               // [2][64]
#define CTRL_BYTES 4096
// f16 tiles (bytes)
#define A_TILE_B (M_TILE * ASTH * 2)          // 3072
#define W_TILE_B (N_OUT  * ASTH * 2)          // 12288
#define STG_B    (A_TILE_B + W_TILE_B)        // 15360
#define SMEM_BYTES (CTRL_BYTES + 2 * STG_B)   // 34816 -> 2 CTAs/SM (regs-limited)

__device__ __forceinline__ uint32_t s2u(const void* p) {
    uint32_t a;
    asm("{ .reg .u64 t; cvta.to.shared.u64 t, %1; cvt.u32.u64 %0, t; }" : "=r"(a) : "l"(p));
    return a;
}
// pack two f32 -> f16x2 reg: lo half = first arg
__device__ __forceinline__ uint32_t packh2(float lo, float hi) {
    uint32_t r;
    asm("cvt.rn.f16x2.f32 %0, %1, %2;" : "=r"(r) : "f"(hi), "f"(lo));
    return r;
}
__device__ __forceinline__ void mma_f16(float* c, const uint32_t a[4], const uint32_t b[2]) {
    asm volatile(
        "mma.sync.aligned.m16n8k16.row.col.f32.f16.f16.f32 "
        "{%0,%1,%2,%3}, {%4,%5,%6,%7}, {%8,%9}, {%0,%1,%2,%3};"
        : "+f"(c[0]), "+f"(c[1]), "+f"(c[2]), "+f"(c[3])
        : "r"(a[0]), "r"(a[1]), "r"(a[2]), "r"(a[3]), "r"(b[0]), "r"(b[1]));
}

__global__ void __launch_bounds__(NTHREADS, 2)
fused_gemm_proj_kernel(const float* __restrict__ x,
                       const float* __restrict__ Wm,
                       const float* __restrict__ bvec,
                       float* __restrict__ out) {
    extern __shared__ __align__(128) float sm[];
    char* smc = reinterpret_cast<char*>(sm);
    const int tid  = threadIdx.x;
    const int wid  = tid >> 5;
    const int lane = tid & 31;
    const int g    = lane >> 2;      // 0..7
    const int tg   = lane & 3;       // 0..3
    const int wr   = wid & 1;        // warp m index (2): 32-row slices
    const int wc   = wid >> 1;       // warp n index (4): 64-col slices
    const int rm   = wr * 32;
    const int cn   = wc * 64;
    const int m0   = blockIdx.x * M_TILE;

    sm[OFF_BIAS + tid] = bvec[tid];

    // per-thread gmem/STS coordinates
    const int ar = tid >> 2;                     // A row 0..63  (wait: 256 threads -> rows 0..63, c 4 each)
    const int ac = (tid & 3) * 4;                // A col 0,4,8,12
    const float* xg = x + (size_t)(m0 + ar) * K_DIM + ac;

    // register staging (1 chunk ahead)
    float4 ra;
    float4 rw[4];
    auto ldg = [&](int k) {
        const int k0 = k * KC;
        ra = *reinterpret_cast<const float4*>(xg + k0);
        #pragma unroll
        for (int i = 0; i < 4; i++) {
            const int ch = tid + NTHREADS * i;
            const int n = ch >> 2, c = (ch & 3) * 4;
            rw[i] = *reinterpret_cast<const float4*>(Wm + (size_t)n * K_DIM + k0 + c);
        }
    };
    auto sts = [&](int s) {
        char* base = smc + CTRL_BYTES + s * STG_B;
        *reinterpret_cast<uint2*>(base + (ar * ASTH + ac) * 2) =
            make_uint2(packh2(ra.x, ra.y), packh2(ra.z, ra.w));
        char* wb = base + A_TILE_B;
        #pragma unroll
        for (int i = 0; i < 4; i++) {
            const int ch = tid + NTHREADS * i;
            const int n = ch >> 2, c = (ch & 3) * 4;
            *reinterpret_cast<uint2*>(wb + (n * ASTH + c) * 2) =
                make_uint2(packh2(rw[i].x, rw[i].y), packh2(rw[i].z, rw[i].w));
        }
    };

    float acc[2][8][4];
    #pragma unroll
    for (int mt = 0; mt < 2; mt++)
        #pragma unroll
        for (int nt = 0; nt < 8; nt++)
            #pragma unroll
            for (int c = 0; c < 4; c++) acc[mt][nt][c] = 0.f;

    // fragment byte offsets (f16 units *2). conflict-free: 12g mod 32 bijective.
    const int afb = ((rm + g) * ASTH + 2 * tg) * 2;   // + mt*16*ASTH*2 (+8*ASTH*2) (+16)
    const int bfb = ((cn + g) * ASTH + 2 * tg) * 2;   // + nt*8*ASTH*2 (+16)

    ldg(0);
    for (int k = 0; k < NCHUNK; k++) {
        const int s = k & 1;
        sts(s);
        if (k + 1 < NCHUNK) ldg(k + 1);
        __syncthreads();

        const char* base = smc + CTRL_BYTES + s * STG_B;
        const char* ap = base + afb;
        const char* bp = base + A_TILE_B + bfb;

        uint32_t bf[8][2];
        #pragma unroll
        for (int nt = 0; nt < 8; nt++) {
            bf[nt][0] = *reinterpret_cast<const uint32_t*>(bp + nt * 8 * ASTH * 2);
            bf[nt][1] = *reinterpret_cast<const uint32_t*>(bp + nt * 8 * ASTH * 2 + 16);
        }
        #pragma unroll
        for (int mt = 0; mt < 2; mt++) {
            uint32_t af[4];
            af[0] = *reinterpret_cast<const uint32_t*>(ap + mt * 16 * ASTH * 2);
            af[1] = *reinterpret_cast<const uint32_t*>(ap + (mt * 16 + 8) * ASTH * 2);
            af[2] = *reinterpret_cast<const uint32_t*>(ap + mt * 16 * ASTH * 2 + 16);
            af[3] = *reinterpret_cast<const uint32_t*>(ap + (mt * 16 + 8) * ASTH * 2 + 16);
            #pragma unroll
            for (int nt = 0; nt < 8; nt++)
                mma_f16(acc[mt][nt], af, bf[nt]);
        }
        // single barrier per chunk is sufficient with 2 stages:
        // a warp can only start writing stage s' after the barrier that
        // guaranteed all warps finished reading s' (two iterations ago).
    }
    __syncthreads();

    // ---------------- fused projection epilogue ----------------
    float bb[8][2];
    #pragma unroll
    for (int nt = 0; nt < 8; nt++) {
        bb[nt][0] = sm[OFF_BIAS + cn + nt * 8 + tg * 2];
        bb[nt][1] = sm[OFF_BIAS + cn + nt * 8 + tg * 2 + 1];
    }

    // pass 1: per-row partials over this warp's 64 columns
    #pragma unroll
    for (int mt = 0; mt < 2; mt++) {
        #pragma unroll
        for (int h = 0; h < 2; h++) {
            float t = 0.f, zz = 0.f;
            #pragma unroll
            for (int nt = 0; nt < 8; nt++) {
                const float z0 = acc[mt][nt][h * 2]     - bb[nt][0];
                const float z1 = acc[mt][nt][h * 2 + 1] - bb[nt][1];
                t += z0 + z1;
                zz = fmaf(z0, z0, zz);
                zz = fmaf(z1, z1, zz);
            }
            #pragma unroll
            for (int o = 1; o <= 2; o <<= 1) {          // reduce over tg (4 lanes)
                t  += __shfl_xor_sync(0xffffffffu, t,  o);
                zz += __shfl_xor_sync(0xffffffffu, zz, o);
            }
            if (tg == 0) {
                const int rloc = rm + mt * 16 + g + h * 8;
                sm[OFF_PT  + wc * 64 + rloc] = t;
                sm[OFF_PZZ + wc * 64 + rloc] = zz;
            }
        }
    }
    __syncthreads();

    if (tid < 64) {
        const float t  = sm[OFF_PT + tid] + sm[OFF_PT + 64 + tid] +
                         sm[OFF_PT + 128 + tid] + sm[OFF_PT + 192 + tid];
        const float zz = sm[OFF_PZZ + tid] + sm[OFF_PZZ + 64 + tid] +
                         sm[OFF_PZZ + 128 + tid] + sm[OFF_PZZ + 192 + tid];
        const float S = 0.1f, R2 = 0.02f, invN = 1.0f / 256.0f;
        const float tc = fminf(fmaxf(t, -S), S);
        const float d1 = (tc - t) * invN;
        const float s1 = fmaf(fmaf(256.f, d1, 2.f * t), d1, zz);
        const bool ok1 = s1 <= R2;
        const float znorm = sqrtf(fmaxf(zz, 1e-12f));
        const float scale = fminf(1.f, 0.141421356237309515f / znorm);
        const bool ok2 = fabsf(t) * scale <= S;
        const float denom = fmaxf(fmaf(256.f, zz, -t * t), 1e-12f);
        const float c3 = sqrtf((256.f * R2 - S * S) / denom);
        const float sp = (t > 0.f) ? S : ((t < 0.f) ? -S : 0.f);
        const float b3 = fmaf(-c3, t, sp) * invN;
        sm[OFF_AB + tid]      = ok1 ? 1.f : (ok2 ? scale : c3);   // alpha
        sm[OFF_AB + 64 + tid] = ok1 ? d1  : (ok2 ? 0.f   : b3);   // beta
    }
    __syncthreads();

    // pass 2: y = alpha*z + beta, float2 stores
    #pragma unroll
    for (int mt = 0; mt < 2; mt++) {
        #pragma unroll
        for (int h = 0; h < 2; h++) {
            const int rloc  = rm + mt * 16 + g + h * 8;
            const float al  = sm[OFF_AB + rloc];
            const float be  = sm[OFF_AB + 64 + rloc];
            float* op = out + (size_t)(m0 + rloc) * N_OUT + cn + tg * 2;
            #pragma unroll
            for (int nt = 0; nt < 8; nt++) {
                float2 v;
                v.x = fmaf(al, acc[mt][nt][h * 2]     - bb[nt][0], be);
                v.y = fmaf(al, acc[mt][nt][h * 2 + 1] - bb[nt][1], be);
                *reinterpret_cast<float2*>(op + nt * 8) = v;
            }
        }
    }
}

extern "C" void kernel_launch(void* const* d_in, const int* in_sizes, int n_in,
                              void* d_out, int out_size) {
    const float* x = (const float*)d_in[0];   // [B, 512]
    const float* W = (const float*)d_in[1];   // [256, 512]
    const float* b = (const float*)d_in[2];   // [256]
    float* out = (float*)d_out;               // [B, 256]
    const int Brows = in_sizes[0] / K_DIM;

    static bool attr_set = false;
    if (!attr_set) {
        cudaFuncSetAttribute(fused_gemm_proj_kernel,
                             cudaFuncAttributeMaxDynamicSharedMemorySize, SMEM_BYTES);
        attr_set = true;
    }
    fused_gemm_proj_kernel<<<Brows / M_TILE, NTHREADS, SMEM_BYTES>>>(x, W, b, out);
}